// round 4
// baseline (speedup 1.0000x reference)
#include <cuda_runtime.h>

#define BB 4
#define SS 512
#define HH 128

typedef unsigned long long u64;

// packed dual-fp32 FMA: acc = a*b + acc (per 32-bit component)
__device__ __forceinline__ void ffma2(u64 &acc, u64 a, u64 b) {
    asm("fma.rn.f32x2 %0, %1, %2, %0;" : "+l"(acc) : "l"(a), "l"(b));
}
__device__ __forceinline__ u64 pk2(float v) {  // {v, v}
    u64 r; asm("mov.b64 %0, {%1, %2};" : "=l"(r) : "f"(v), "f"(v)); return r;
}
__device__ __forceinline__ u64 pk2b(float lo, float hi) {
    u64 r; asm("mov.b64 %0, {%1, %2};" : "=l"(r) : "f"(lo), "f"(hi)); return r;
}
__device__ __forceinline__ float2 upk(u64 v) {
    float2 r; asm("mov.b64 {%0, %1}, %2;" : "=f"(r.x), "=f"(r.y) : "l"(v)); return r;
}

// One WARP handles 2 output rows (t0, t0+1): all 128 h columns, 4 per lane.
// Block = 2 independent warps. Grid = 2048/4 = 512 blocks.
__global__ __launch_bounds__(64) void align_kernel(
    const float* __restrict__ x, const float* __restrict__ ref,
    const float* __restrict__ Wa, const float* __restrict__ Wb,
    const float* __restrict__ b1, const float* __restrict__ W2,
    const float* __restrict__ b2, const float* __restrict__ Wp1,
    const float* __restrict__ bp1, const float* __restrict__ Wp2,
    const float* __restrict__ bp2, float* __restrict__ out)
{
    const int tid = threadIdx.x;
    const int w   = tid >> 5;
    const int l   = tid & 31;
    const int g   = blockIdx.x * 4 + w * 2;   // first output row (even), never straddles batch
    const int b   = g >> 9;
    const int t0  = g & (SS - 1);

    // [warp][x rows 0..2 | ref rows 3..5][k], each element a duplicated {v,v} pair
    __shared__ u64 rows[2][6][HH];
    u64* rw = &rows[w][0][0];

    // load rows t0-1, t0, t0+1; keep the float4 (this lane's 4 h-columns) for output
    float4 xv[3], rv[3];
    #pragma unroll
    for (int r = 0; r < 3; r++) {
        int t  = t0 - 1 + r;
        int tc = t < 0 ? 0 : t;
        const float4* xp = (const float4*)&x[(size_t)(b * SS + tc) * HH];
        const float4* rp = (const float4*)&ref[(size_t)(b * SS + tc) * HH];
        xv[r] = xp[l];
        rv[r] = rp[l];
        rw[r * HH + 4 * l + 0] = pk2(xv[r].x);
        rw[r * HH + 4 * l + 1] = pk2(xv[r].y);
        rw[r * HH + 4 * l + 2] = pk2(xv[r].z);
        rw[r * HH + 4 * l + 3] = pk2(xv[r].w);
        rw[(3 + r) * HH + 4 * l + 0] = pk2(rv[r].x);
        rw[(3 + r) * HH + 4 * l + 1] = pk2(rv[r].y);
        rw[(3 + r) * HH + 4 * l + 2] = pk2(rv[r].z);
        rw[(3 + r) * HH + 4 * l + 3] = pk2(rv[r].w);
    }
    __syncwarp();

    // accumulators: A[r] = x_row_r @ Wa + b1, C[r] = ref_row_r @ Wb, P[i] = x_row_{i+1} @ Wp1 + bp1
    // each dot held as 2 packed pairs covering this lane's h = 4l..4l+3
    const float4 b1v  = ((const float4*)b1)[l];
    const float4 bp1v = ((const float4*)bp1)[l];
    u64 A[3][2], C[3][2], P[2][2];
    #pragma unroll
    for (int r = 0; r < 3; r++) {
        A[r][0] = pk2b(b1v.x, b1v.y);  A[r][1] = pk2b(b1v.z, b1v.w);
        C[r][0] = 0ULL;                C[r][1] = 0ULL;   // {0.f, 0.f}
    }
    #pragma unroll
    for (int i = 0; i < 2; i++) {
        P[i][0] = pk2b(bp1v.x, bp1v.y);  P[i][1] = pk2b(bp1v.z, bp1v.w);
    }

    const ulonglong2* __restrict__ Wa2 = (const ulonglong2*)Wa;   // [k*32 + l] -> pairs (h0,h1),(h2,h3)
    const ulonglong2* __restrict__ Wb2 = (const ulonglong2*)Wb;
    const ulonglong2* __restrict__ Wp2_ = (const ulonglong2*)Wp1;

    #pragma unroll 4
    for (int k = 0; k < HH; k++) {
        const ulonglong2 wa = Wa2[k * 32 + l];
        const ulonglong2 wb = Wb2[k * 32 + l];
        const ulonglong2 wp = Wp2_[k * 32 + l];
        const u64 xk0 = rw[0 * HH + k], xk1 = rw[1 * HH + k], xk2 = rw[2 * HH + k];
        const u64 rk0 = rw[3 * HH + k], rk1 = rw[4 * HH + k], rk2 = rw[5 * HH + k];
        ffma2(A[0][0], wa.x, xk0);  ffma2(A[0][1], wa.y, xk0);
        ffma2(A[1][0], wa.x, xk1);  ffma2(A[1][1], wa.y, xk1);
        ffma2(A[2][0], wa.x, xk2);  ffma2(A[2][1], wa.y, xk2);
        ffma2(C[0][0], wb.x, rk0);  ffma2(C[0][1], wb.y, rk0);
        ffma2(C[1][0], wb.x, rk1);  ffma2(C[1][1], wb.y, rk1);
        ffma2(C[2][0], wb.x, rk2);  ffma2(C[2][1], wb.y, rk2);
        ffma2(P[0][0], wp.x, xk1);  ffma2(P[0][1], wp.y, xk1);
        ffma2(P[1][0], wp.x, xk2);  ffma2(P[1][1], wp.y, xk2);
    }

    // unpack to scalars for the (tiny) tail
    float a_[3][4], c_[3][4], p_[2][4];
    #pragma unroll
    for (int r = 0; r < 3; r++) {
        float2 u0 = upk(A[r][0]), u1 = upk(A[r][1]);
        a_[r][0] = u0.x; a_[r][1] = u0.y; a_[r][2] = u1.x; a_[r][3] = u1.y;
        float2 v0 = upk(C[r][0]), v1 = upk(C[r][1]);
        c_[r][0] = v0.x; c_[r][1] = v0.y; c_[r][2] = v1.x; c_[r][3] = v1.y;
    }
    #pragma unroll
    for (int i = 0; i < 2; i++) {
        float2 u0 = upk(P[i][0]), u1 = upk(P[i][1]);
        p_[i][0] = fmaxf(u0.x, 0.f); p_[i][1] = fmaxf(u0.y, 0.f);
        p_[i][2] = fmaxf(u1.x, 0.f); p_[i][3] = fmaxf(u1.y, 0.f);
    }

    const float4 w2v = ((const float4*)W2)[l];
    float w2a[4] = {w2v.x, w2v.y, w2v.z, w2v.w};
    float wp2v[12];
    {
        const float4* q = (const float4*)&Wp2[12 * l];   // h = 4l..4l+3, 3 each; 16B aligned
        float4 q0 = q[0], q1 = q[1], q2 = q[2];
        wp2v[0]=q0.x; wp2v[1]=q0.y; wp2v[2] =q0.z; wp2v[3] =q0.w;
        wp2v[4]=q1.x; wp2v[5]=q1.y; wp2v[6] =q1.z; wp2v[7] =q1.w;
        wp2v[8]=q2.x; wp2v[9]=q2.y; wp2v[10]=q2.z; wp2v[11]=q2.w;
    }
    const float b2s   = b2[0];
    const float bp2v0 = bp2[0], bp2v1 = bp2[1], bp2v2 = bp2[2];

    #pragma unroll
    for (int i = 0; i < 2; i++) {
        const int t = t0 + i;
        float vv[6] = {0.f, 0.f, 0.f, 0.f, 0.f, 0.f};
        #pragma unroll
        for (int j = 0; j < 4; j++) {
            const float at = a_[i + 1][j], am = a_[i][j];
            const float ct = c_[i + 1][j], cm = c_[i][j];
            vv[0] += fmaxf(at + ct, 0.f) * w2a[j];   // A[t, t]
            vv[1] += fmaxf(am + ct, 0.f) * w2a[j];   // A[t-1, t]
            vv[2] += fmaxf(at + cm, 0.f) * w2a[j];   // A[t, t-1]
            const float pj = p_[i][j];
            vv[3] += pj * wp2v[3 * j + 0];
            vv[4] += pj * wp2v[3 * j + 1];
            vv[5] += pj * wp2v[3 * j + 2];
        }
        #pragma unroll
        for (int j = 0; j < 6; j++) {
            float s = vv[j];
            s += __shfl_xor_sync(0xffffffffu, s, 16);
            s += __shfl_xor_sync(0xffffffffu, s, 8);
            s += __shfl_xor_sync(0xffffffffu, s, 4);
            s += __shfl_xor_sync(0xffffffffu, s, 2);
            s += __shfl_xor_sync(0xffffffffu, s, 1);
            vv[j] = s;   // all lanes hold the sum
        }

        // scalar decision, computed redundantly on all lanes (no broadcast needed)
        int   op    = -1;     // -1 => copy x (t == 0)
        float alpha = 0.f;
        const float Ad = 1.0f / (1.0f + expf(-(vv[0] + b2s)));
        if (t != 0) {
            const float Ai   = 1.0f / (1.0f + expf(-(vv[1] + b2s)));
            const float Adel = 1.0f / (1.0f + expf(-(vv[2] + b2s)));
            const float l0 = vv[3] + bp2v0;
            const float l1 = vv[4] + bp2v1;
            const float l2 = vv[5] + bp2v2;
            const float mx  = fmaxf(l0, fmaxf(l1, l2));
            const float lse = mx + logf(expf(l0 - mx) + expf(l1 - mx) + expf(l2 - mx));
            const float m   = Ad   * (l0 - lse);
            const float ins = Ai   * (l1 - lse);
            const float del = Adel * (l2 - lse);
            if (m >= ins && m >= del) op = 0;      // first-max tie-break == jnp.argmax
            else if (ins >= del)      op = 1;
            else                      op = 2;
            alpha = Ad;
        }

        const float4 cx = xv[i + 1];   // x[t]
        const float4 cr = rv[i + 1];   // ref[t]
        const float4 px = xv[i];       // x[t-1]
        float4 o;
        if (op < 0) {
            o = cx;
        } else if (op == 0) {
            o.x = (1.f - alpha) * cx.x + alpha * cr.x;
            o.y = (1.f - alpha) * cx.y + alpha * cr.y;
            o.z = (1.f - alpha) * cx.z + alpha * cr.z;
            o.w = (1.f - alpha) * cx.w + alpha * cr.w;
        } else if (op == 1) {
            o = cr;
        } else {
            o = px;
        }
        ((float4*)&out[(size_t)(b * SS + t) * HH])[l] = o;
    }
}

extern "C" void kernel_launch(void* const* d_in, const int* in_sizes, int n_in,
                              void* d_out, int out_size) {
    const float* x   = (const float*)d_in[0];
    const float* ref = (const float*)d_in[1];
    const float* Wa  = (const float*)d_in[2];
    const float* Wb  = (const float*)d_in[3];
    const float* b1  = (const float*)d_in[4];
    const float* W2  = (const float*)d_in[5];
    const float* b2  = (const float*)d_in[6];
    const float* Wp1 = (const float*)d_in[7];
    const float* bp1 = (const float*)d_in[8];
    const float* Wp2 = (const float*)d_in[9];
    const float* bp2 = (const float*)d_in[10];

    dim3 grid(BB * SS / 4);   // 512 blocks, 4 rows each
    dim3 block(64);           // 2 independent warps per block
    align_kernel<<<grid, block>>>(x, ref, Wa, Wb, b1, W2, b2,
                                  Wp1, bp1, Wp2, bp2, (float*)d_out);
}

// round 5
// speedup vs baseline: 1.5192x; 1.5192x over previous
#include <cuda_runtime.h>

#define BB 4
#define SS 512
#define HH 128

// 512 blocks, 512 threads. Block owns 4 output rows (t0..t0+3).
// Thread (h = tid&127, q = tid>>7) accumulates the 14 live dot products
// (a[t0-1..t0+3], c[t0-1..t0+3], p[t0..t0+3]) over k-quarter q.
// Partials combined through smem; q==0 slice runs the scalar tail.
__global__ __launch_bounds__(512) void align_kernel(
    const float* __restrict__ x, const float* __restrict__ ref,
    const float* __restrict__ Wa, const float* __restrict__ Wb,
    const float* __restrict__ b1, const float* __restrict__ W2,
    const float* __restrict__ b2, const float* __restrict__ Wp1,
    const float* __restrict__ bp1, const float* __restrict__ Wp2,
    const float* __restrict__ bp2, float* __restrict__ out)
{
    const int tid = threadIdx.x;
    const int q   = tid >> 7;        // k-quarter 0..3
    const int h   = tid & 127;       // hidden column
    const int g0  = blockIdx.x * 4;  // first output row
    const int b   = g0 >> 9;
    const int t0  = g0 & (SS - 1);

    __shared__ float2 rows_s[5][HH];        // {x, ref}, rows t0-1 .. t0+3
    __shared__ float  part[3][14][HH];      // partials from q = 1..3
    __shared__ float  red[4][24];           // per-warp reduced scalars (q==0 tail)
    __shared__ float  rowvals[4][2];        // [op_code, alpha]

    // ---- cooperative row load ----
    for (int r = q; r < 5; r += 4) {
        int t  = t0 - 1 + r;
        int tc = t < 0 ? 0 : t;
        const size_t gi = (size_t)(b * SS + tc) * HH + h;
        rows_s[r][h] = make_float2(x[gi], ref[gi]);
    }
    __syncthreads();

    // ---- k-quarter mainloop ----
    float A[5], C[5], P[4];
    const float ab = (q == 0) ? b1[h]  : 0.0f;
    const float pb = (q == 0) ? bp1[h] : 0.0f;
    #pragma unroll
    for (int r = 0; r < 5; r++) { A[r] = ab; C[r] = 0.0f; }
    #pragma unroll
    for (int r = 0; r < 4; r++) P[r] = pb;

    const int kbase = q * 32;
    #pragma unroll 8
    for (int kk = 0; kk < 32; kk++) {
        const int k = kbase + kk;
        const float wa = Wa[k * HH + h];
        const float wb = Wb[k * HH + h];
        const float wp = Wp1[k * HH + h];
        #pragma unroll
        for (int r = 0; r < 5; r++) {
            const float2 v = rows_s[r][k];
            A[r] = fmaf(v.x, wa, A[r]);
            C[r] = fmaf(v.y, wb, C[r]);
            if (r >= 1) P[r - 1] = fmaf(v.x, wp, P[r - 1]);
        }
    }

    // ---- publish partials (q = 1..3) ----
    if (q != 0) {
        #pragma unroll
        for (int r = 0; r < 5; r++) {
            part[q - 1][r][h]     = A[r];
            part[q - 1][5 + r][h] = C[r];
        }
        #pragma unroll
        for (int r = 0; r < 4; r++) part[q - 1][10 + r][h] = P[r];
    }
    __syncthreads();

    if (q == 0) {
        // ---- combine ----
        #pragma unroll
        for (int r = 0; r < 5; r++) {
            A[r] += part[0][r][h] + part[1][r][h] + part[2][r][h];
            C[r] += part[0][5 + r][h] + part[1][5 + r][h] + part[2][5 + r][h];
        }
        #pragma unroll
        for (int r = 0; r < 4; r++) {
            P[r] += part[0][10 + r][h] + part[1][10 + r][h] + part[2][10 + r][h];
            P[r]  = fmaxf(P[r], 0.0f);
        }

        const float w2   = W2[h];
        const float wp20 = Wp2[h * 3 + 0];
        const float wp21 = Wp2[h * 3 + 1];
        const float wp22 = Wp2[h * 3 + 2];

        const int wid  = tid >> 5;   // 0..3 within q==0 slice
        const int lane = tid & 31;

        // ---- batched reduction: 4 rows x 6 components ----
        #pragma unroll
        for (int i = 0; i < 4; i++) {
            float v[6];
            v[0] = fmaxf(A[i + 1] + C[i + 1], 0.0f) * w2;  // A[t, t]
            v[1] = fmaxf(A[i]     + C[i + 1], 0.0f) * w2;  // A[t-1, t]  (insert)
            v[2] = fmaxf(A[i + 1] + C[i],     0.0f) * w2;  // A[t, t-1]  (delete)
            v[3] = P[i] * wp20;
            v[4] = P[i] * wp21;
            v[5] = P[i] * wp22;
            #pragma unroll
            for (int j = 0; j < 6; j++) {
                float s = v[j];
                s += __shfl_xor_sync(0xffffffffu, s, 16);
                s += __shfl_xor_sync(0xffffffffu, s, 8);
                s += __shfl_xor_sync(0xffffffffu, s, 4);
                s += __shfl_xor_sync(0xffffffffu, s, 2);
                s += __shfl_xor_sync(0xffffffffu, s, 1);
                if (lane == 0) red[wid][i * 6 + j] = s;
            }
        }
        asm volatile("bar.sync 1, 128;" ::: "memory");

        // ---- warp 0: combine warp partials, 4 decisions in parallel ----
        if (tid < 32) {
            float s = 0.0f;
            if (lane < 24)
                s = red[0][lane] + red[1][lane] + red[2][lane] + red[3][lane];
            const float s0 = __shfl_sync(0xffffffffu, s, lane * 6 + 0);
            const float s1 = __shfl_sync(0xffffffffu, s, lane * 6 + 1);
            const float s2 = __shfl_sync(0xffffffffu, s, lane * 6 + 2);
            const float s3 = __shfl_sync(0xffffffffu, s, lane * 6 + 3);
            const float s4 = __shfl_sync(0xffffffffu, s, lane * 6 + 4);
            const float s5 = __shfl_sync(0xffffffffu, s, lane * 6 + 5);

            if (lane < 4) {
                const int t = t0 + lane;
                float op_code, alpha;
                const float Ad = 1.0f / (1.0f + expf(-(s0 + b2[0])));
                if (t == 0) {
                    op_code = -1.0f;  // copy x[:,0]
                    alpha   = 0.0f;
                } else {
                    const float Ai   = 1.0f / (1.0f + expf(-(s1 + b2[0])));
                    const float Adel = 1.0f / (1.0f + expf(-(s2 + b2[0])));
                    const float l0 = s3 + bp2[0];
                    const float l1 = s4 + bp2[1];
                    const float l2 = s5 + bp2[2];
                    const float mx  = fmaxf(l0, fmaxf(l1, l2));
                    const float lse = mx + logf(expf(l0 - mx) + expf(l1 - mx) + expf(l2 - mx));
                    const float m   = Ad   * (l0 - lse);
                    const float ins = Ai   * (l1 - lse);
                    const float del = Adel * (l2 - lse);
                    int op;
                    if (m >= ins && m >= del) op = 0;  // first-max == jnp.argmax
                    else if (ins >= del)      op = 1;
                    else                      op = 2;
                    op_code = (float)op;
                    alpha   = Ad;
                }
                rowvals[lane][0] = op_code;
                rowvals[lane][1] = alpha;
            }
        }
        asm volatile("bar.sync 1, 128;" ::: "memory");

        // ---- write 4 output rows ----
        #pragma unroll
        for (int i = 0; i < 4; i++) {
            const float fop   = rowvals[i][0];
            const float alpha = rowvals[i][1];
            const float2 cur  = rows_s[i + 1][h];
            const float  xm1  = rows_s[i][h].x;
            float o;
            if (fop < -0.5f)      o = cur.x;                                  // t == 0
            else if (fop < 0.5f)  o = (1.0f - alpha) * cur.x + alpha * cur.y; // match
            else if (fop < 1.5f)  o = cur.y;                                  // insert
            else                  o = xm1;                                    // delete
            out[(size_t)(b * SS + t0 + i) * HH + h] = o;
        }
    }
}

extern "C" void kernel_launch(void* const* d_in, const int* in_sizes, int n_in,
                              void* d_out, int out_size) {
    const float* x   = (const float*)d_in[0];
    const float* ref = (const float*)d_in[1];
    const float* Wa  = (const float*)d_in[2];
    const float* Wb  = (const float*)d_in[3];
    const float* b1  = (const float*)d_in[4];
    const float* W2  = (const float*)d_in[5];
    const float* b2  = (const float*)d_in[6];
    const float* Wp1 = (const float*)d_in[7];
    const float* bp1 = (const float*)d_in[8];
    const float* Wp2 = (const float*)d_in[9];
    const float* bp2 = (const float*)d_in[10];

    dim3 grid(BB * SS / 4);   // 512 blocks, 4 rows each
    dim3 block(512);          // 128 h-threads x 4 k-quarters
    align_kernel<<<grid, block>>>(x, ref, Wa, Wb, b1, W2, b2,
                                  Wp1, bp1, Wp2, bp2, (float*)d_out);
}